// round 4
// baseline (speedup 1.0000x reference)
#include <cuda_runtime.h>
#include <cuda_bf16.h>
#include <cstdint>

#define D_    512
#define NQ_   16384
#define NL_   1024

// ============================ scratch ============================
__device__ __nv_bfloat16 g_gh[NQ_ * D_];   // guide token-major hi
__device__ __nv_bfloat16 g_gl[NQ_ * D_];
__device__ __nv_bfloat16 g_lh[NL_ * D_];   // low token-major hi
__device__ __nv_bfloat16 g_ll[NL_ * D_];
__device__ __nv_bfloat16 g_Wh[4][D_ * D_]; // q,k,v,m weights hi
__device__ __nv_bfloat16 g_Wl[4][D_ * D_];
__device__ float g_q[NQ_ * D_];
__device__ float g_K[NL_ * D_];
__device__ float g_V[NL_ * D_];
__device__ __nv_bfloat16 g_mh[NQ_ * D_];   // msg hi
__device__ __nv_bfloat16 g_ml[NQ_ * D_];
__device__ float g_mT[NQ_ * D_];

// ============================ helpers ============================
__device__ __forceinline__ uint32_t smem_u32(const void* p) {
    uint32_t a;
    asm("{ .reg .u64 t; cvta.to.shared.u64 t, %1; cvt.u32.u64 %0, t; }" : "=r"(a) : "l"(p));
    return a;
}
__device__ __forceinline__ void cp16(uint32_t s, const void* g) {
    asm volatile("cp.async.cg.shared.global [%0], [%1], 16;" :: "r"(s), "l"(g));
}
#define CP_COMMIT() asm volatile("cp.async.commit_group;" ::: "memory")
#define CP_WAIT(n)  asm volatile("cp.async.wait_group %0;" :: "n"(n) : "memory")

__device__ __forceinline__ void ldsm_x4(uint32_t* r, uint32_t addr) {
    asm volatile("ldmatrix.sync.aligned.m8n8.x4.shared.b16 {%0,%1,%2,%3}, [%4];"
                 : "=r"(r[0]), "=r"(r[1]), "=r"(r[2]), "=r"(r[3]) : "r"(addr));
}
__device__ __forceinline__ void mma_bf16(float* d, const uint32_t* a, uint32_t b0, uint32_t b1) {
    asm volatile(
        "mma.sync.aligned.m16n8k16.row.col.f32.bf16.bf16.f32 "
        "{%0,%1,%2,%3}, {%4,%5,%6,%7}, {%8,%9}, {%0,%1,%2,%3};"
        : "+f"(d[0]), "+f"(d[1]), "+f"(d[2]), "+f"(d[3])
        : "r"(a[0]), "r"(a[1]), "r"(a[2]), "r"(a[3]), "r"(b0), "r"(b1));
}

// ============================ converts ============================
__global__ __launch_bounds__(256)
void convert_split(const float* __restrict__ x, __nv_bfloat16* __restrict__ hi,
                   __nv_bfloat16* __restrict__ lo, int n) {
    int i = blockIdx.x * 256 + threadIdx.x;
    if (i < n) {
        float v = x[i];
        __nv_bfloat16 h = __float2bfloat16(v);
        hi[i] = h;
        lo[i] = __float2bfloat16(v - __bfloat162float(h));
    }
}

// [512 c][N] fp32 -> [N][512] bf16 hi/lo
__global__ __launch_bounds__(256)
void transpose_split(const float* __restrict__ x, __nv_bfloat16* __restrict__ hi,
                     __nv_bfloat16* __restrict__ lo, int N) {
    __shared__ float t[32][33];
    const int n0 = blockIdx.x * 32, c0 = blockIdx.y * 32;
    const int tx = threadIdx.x, ty = threadIdx.y;
#pragma unroll
    for (int j = 0; j < 32; j += 8)
        t[ty + j][tx] = x[(size_t)(c0 + ty + j) * N + n0 + tx];
    __syncthreads();
#pragma unroll
    for (int j = 0; j < 32; j += 8) {
        float v = t[tx][ty + j];
        __nv_bfloat16 h = __float2bfloat16(v);
        size_t o = (size_t)(n0 + ty + j) * D_ + c0 + tx;
        hi[o] = h;
        lo[o] = __float2bfloat16(v - __bfloat162float(h));
    }
}

// ============================ GEMM (cp.async pipelined) ============================
// C[m,n] = sum_k (Ah+Al)[m,k] * (Bh+Bl)[n,k]; A:[M][512] bf16, B:[512][512] bf16.
// CTA 128m x 128n, k-chunk 64, double-buffered. 8 warps 2m x 4n, warp 64m x 32n.
// 3 MMAs: hh + hl + lh.
__global__ __launch_bounds__(256, 1)
void gemm_pipe(const __nv_bfloat16* __restrict__ Ah, const __nv_bfloat16* __restrict__ Al,
               const __nv_bfloat16* __restrict__ Bh, const __nv_bfloat16* __restrict__ Bl,
               float* __restrict__ C) {
    extern __shared__ char sm[];
    const int tid = threadIdx.x, lane = tid & 31, warp = tid >> 5;
    const int wm = (warp & 1) * 64, wn = (warp >> 1) * 32;
    const int m0 = blockIdx.x * 128, n0 = blockIdx.y * 128;
    const uint32_t s0 = smem_u32(sm);
    // per stage: Ah(18432) Al(18432) Bh(18432) Bl(18432); stage stride 73728

    const int l_row = tid >> 3, l_c16 = tid & 7;   // 32 rows per pass, 4 passes

#define LOAD_STAGE(BUF, K0) do {                                                \
    const uint32_t sb = s0 + (BUF) * 73728u;                                    \
    _Pragma("unroll")                                                           \
    for (int it = 0; it < 4; it++) {                                            \
        const int row = l_row + it * 32;                                        \
        const uint32_t so = (uint32_t)(row * 144 + l_c16 * 16);                 \
        const size_t ga = (size_t)(m0 + row) * 512 + (K0) + l_c16 * 8;          \
        const size_t gb = (size_t)(n0 + row) * 512 + (K0) + l_c16 * 8;          \
        cp16(sb + so,           Ah + ga);                                       \
        cp16(sb + 18432u + so,  Al + ga);                                       \
        cp16(sb + 36864u + so,  Bh + gb);                                       \
        cp16(sb + 55296u + so,  Bl + gb);                                       \
    }                                                                           \
} while (0)

    const uint32_t aoff0 = (uint32_t)((wm + (lane & 15)) * 144 + ((lane >> 4) & 1) * 16);
    const uint32_t boff0 = (uint32_t)((wn + (lane & 7) + ((lane >> 4) & 1) * 8) * 144 +
                                      ((lane >> 3) & 1) * 16);

    float acc[4][4][4];
#pragma unroll
    for (int i = 0; i < 4; i++)
#pragma unroll
        for (int j = 0; j < 4; j++)
#pragma unroll
            for (int r = 0; r < 4; r++) acc[i][j][r] = 0.f;

    LOAD_STAGE(0, 0);
    CP_COMMIT();

    for (int ch = 0; ch < 8; ch++) {
        if (ch < 7) { LOAD_STAGE((ch + 1) & 1, (ch + 1) * 64); CP_COMMIT(); }
        if (ch < 7) { CP_WAIT(1); } else { CP_WAIT(0); }
        __syncthreads();

        const uint32_t base = s0 + (uint32_t)(ch & 1) * 73728u;
#pragma unroll
        for (int ks = 0; ks < 4; ks++) {
            uint32_t ah[4][4], al[4][4], bh[2][4], bl[2][4];
#pragma unroll
            for (int mi = 0; mi < 4; mi++) {
                const uint32_t ao = aoff0 + mi * 16 * 144 + ks * 32;
                ldsm_x4(ah[mi], base + ao);
                ldsm_x4(al[mi], base + 18432u + ao);
            }
#pragma unroll
            for (int nt = 0; nt < 2; nt++) {
                const uint32_t bo = boff0 + nt * 16 * 144 + ks * 32;
                ldsm_x4(bh[nt], base + 36864u + bo);
                ldsm_x4(bl[nt], base + 55296u + bo);
            }
#pragma unroll
            for (int mi = 0; mi < 4; mi++) {
#pragma unroll
                for (int j = 0; j < 4; j++) {
                    const uint32_t bh0 = bh[j >> 1][(j & 1) * 2];
                    const uint32_t bh1 = bh[j >> 1][(j & 1) * 2 + 1];
                    const uint32_t bl0 = bl[j >> 1][(j & 1) * 2];
                    const uint32_t bl1 = bl[j >> 1][(j & 1) * 2 + 1];
                    mma_bf16(acc[mi][j], ah[mi], bh0, bh1);
                    mma_bf16(acc[mi][j], ah[mi], bl0, bl1);
                    mma_bf16(acc[mi][j], al[mi], bh0, bh1);
                }
            }
        }
        __syncthreads();
    }

    const int g = lane >> 2, t4 = lane & 3;
#pragma unroll
    for (int mi = 0; mi < 4; mi++) {
#pragma unroll
        for (int j = 0; j < 4; j++) {
            const int row = m0 + wm + mi * 16 + g;
            const int col = n0 + wn + j * 8 + 2 * t4;
            *(float2*)(C + (size_t)row * 512 + col)       = make_float2(acc[mi][j][0], acc[mi][j][1]);
            *(float2*)(C + (size_t)(row + 8) * 512 + col) = make_float2(acc[mi][j][2], acc[mi][j][3]);
        }
    }
#undef LOAD_STAGE
}

// ============================ attention ============================
// q:[NQ,512] fp32; K,V:[NL,512] fp32; out msg hi/lo bf16 [NQ,512].
// One block per 4x4 tile (shared 3x3 window). 128 thr = 16 q x 8 heads.
// q loaded straight to registers; smem only K/V (37 KB) -> ~6 CTAs/SM.
__global__ __launch_bounds__(128)
void attn(const float* __restrict__ q, const float* __restrict__ Kb,
          const float* __restrict__ Vb,
          __nv_bfloat16* __restrict__ mh, __nv_bfloat16* __restrict__ ml) {
    extern __shared__ float4 s4[];
    float4* ks = s4;                 // 9 x 129
    float4* vs = ks + 9 * 129;       // 9 x 129

    const int by = blockIdx.y, bx = blockIdx.x;
    const int tid = threadIdx.x;

    for (int t = tid; t < 1152; t += 128) {
        const int k = t >> 7, i = t & 127;
        const int yy = min(max(by + k / 3 - 1, 0), 31);
        const int xx = min(max(bx + k % 3 - 1, 0), 31);
        const int pos = yy * 32 + xx;
        ks[k * 129 + i] = ((const float4*)(Kb + (size_t)pos * D_))[i];
        vs[k * 129 + i] = ((const float4*)(Vb + (size_t)pos * D_))[i];
    }

    const int qi = tid & 15;
    const int h = tid >> 4;
    const int n = (4 * by + (qi >> 2)) * 128 + 4 * bx + (qi & 3);

    float4 qr[16];
    const float4* qg = (const float4*)(q + (size_t)n * D_ + h * 64);
#pragma unroll
    for (int i = 0; i < 16; i++) qr[i] = qg[i];

    __syncthreads();

    float sc[9];
#pragma unroll
    for (int k = 0; k < 9; k++) {
        const float4* kp = ks + k * 129 + h * 16;
        float s = 0.f;
#pragma unroll
        for (int d4 = 0; d4 < 16; d4++) {
            const float4 a = qr[d4], b = kp[d4];
            s = fmaf(a.x, b.x, s); s = fmaf(a.y, b.y, s);
            s = fmaf(a.z, b.z, s); s = fmaf(a.w, b.w, s);
        }
        sc[k] = s * 0.125f;
    }
    float mx = sc[0];
#pragma unroll
    for (int k = 1; k < 9; k++) mx = fmaxf(mx, sc[k]);
    float sum = 0.f;
#pragma unroll
    for (int k = 0; k < 9; k++) { sc[k] = __expf(sc[k] - mx); sum += sc[k]; }
    const float inv = 1.f / sum;
#pragma unroll
    for (int k = 0; k < 9; k++) sc[k] *= inv;

    __nv_bfloat162* oh = (__nv_bfloat162*)(mh + (size_t)n * D_ + h * 64);
    __nv_bfloat162* ol = (__nv_bfloat162*)(ml + (size_t)n * D_ + h * 64);
#pragma unroll 4
    for (int d4 = 0; d4 < 16; d4++) {
        float ax = 0.f, ay = 0.f, az = 0.f, aw = 0.f;
#pragma unroll
        for (int k = 0; k < 9; k++) {
            const float4 v = vs[k * 129 + h * 16 + d4];
            ax = fmaf(sc[k], v.x, ax); ay = fmaf(sc[k], v.y, ay);
            az = fmaf(sc[k], v.z, az); aw = fmaf(sc[k], v.w, aw);
        }
        __nv_bfloat16 hx = __float2bfloat16(ax), hy = __float2bfloat16(ay);
        __nv_bfloat16 hz = __float2bfloat16(az), hw = __float2bfloat16(aw);
        __nv_bfloat162 p0; p0.x = hx; p0.y = hy;
        __nv_bfloat162 p1; p1.x = hz; p1.y = hw;
        oh[d4 * 2 + 0] = p0;
        oh[d4 * 2 + 1] = p1;
        __nv_bfloat162 q0, q1;
        q0.x = __float2bfloat16(ax - __bfloat162float(hx));
        q0.y = __float2bfloat16(ay - __bfloat162float(hy));
        q1.x = __float2bfloat16(az - __bfloat162float(hz));
        q1.y = __float2bfloat16(aw - __bfloat162float(hw));
        ol[d4 * 2 + 0] = q0;
        ol[d4 * 2 + 1] = q1;
    }
}

// ============================ fused LayerNorm + transpose ============================
// One block = 32 tokens. Stats + apply + transposed write in one pass.
__global__ __launch_bounds__(256)
void ln_fused(const float* __restrict__ m, const float* __restrict__ gamma,
              const float* __restrict__ beta, float* __restrict__ out) {
    extern __shared__ float smf[];            // [32][513]
    __shared__ float smu[32], srs[32];
    const int n0 = blockIdx.x * 32;
    const int tid = threadIdx.x, lane = tid & 31, warp = tid >> 5;

    for (int idx = tid; idx < 32 * 128; idx += 256) {
        const int row = idx >> 7, c4 = idx & 127;
        const float4 v = *(const float4*)(m + (size_t)(n0 + row) * 512 + c4 * 4);
        float* d = smf + row * 513 + c4 * 4;
        d[0] = v.x; d[1] = v.y; d[2] = v.z; d[3] = v.w;
    }
    __syncthreads();

#pragma unroll
    for (int t = warp * 4; t < warp * 4 + 4; t++) {
        float s = 0.f, s2 = 0.f;
#pragma unroll
        for (int i = 0; i < 16; i++) {
            const float v = smf[t * 513 + lane + i * 32];
            s += v; s2 += v * v;
        }
#pragma unroll
        for (int o = 16; o; o >>= 1) {
            s  += __shfl_xor_sync(0xFFFFFFFFu, s, o);
            s2 += __shfl_xor_sync(0xFFFFFFFFu, s2, o);
        }
        if (lane == 0) {
            const float mu = s * (1.f / 512.f);
            smu[t] = mu;
            srs[t] = rsqrtf(s2 * (1.f / 512.f) - mu * mu + 1e-5f);
        }
    }
    __syncthreads();

    for (int idx = tid; idx < 32 * 512; idx += 256) {
        const int c = idx >> 5, nl = idx & 31;
        out[(size_t)c * NQ_ + n0 + nl] =
            (smf[nl * 513 + c] - smu[nl]) * srs[nl] * gamma[c] + beta[c];
    }
}

// ============================ launch ============================
extern "C" void kernel_launch(void* const* d_in, const int* in_sizes, int n_in,
                              void* d_out, int out_size) {
    const float* low   = (const float*)d_in[0];
    const float* guide = (const float*)d_in[1];
    const float* Wq    = (const float*)d_in[2];
    const float* Wk    = (const float*)d_in[3];
    const float* Wv    = (const float*)d_in[4];
    const float* Wm    = (const float*)d_in[5];
    const float* gamma = (const float*)d_in[6];
    const float* beta  = (const float*)d_in[7];
    float* out = (float*)d_out;

    __nv_bfloat16 *gh, *gl, *lh, *ll, *Wh, *Wl, *mh, *ml;
    float *qb, *Kb, *Vb, *mT;
    cudaGetSymbolAddress((void**)&gh, g_gh);
    cudaGetSymbolAddress((void**)&gl, g_gl);
    cudaGetSymbolAddress((void**)&lh, g_lh);
    cudaGetSymbolAddress((void**)&ll, g_ll);
    cudaGetSymbolAddress((void**)&Wh, g_Wh);
    cudaGetSymbolAddress((void**)&Wl, g_Wl);
    cudaGetSymbolAddress((void**)&qb, g_q);
    cudaGetSymbolAddress((void**)&Kb, g_K);
    cudaGetSymbolAddress((void**)&Vb, g_V);
    cudaGetSymbolAddress((void**)&mh, g_mh);
    cudaGetSymbolAddress((void**)&ml, g_ml);
    cudaGetSymbolAddress((void**)&mT, g_mT);

    const int SM_GEMM = 2 * 73728;       // 147456
    const int SM_ATTN = 18 * 129 * 16;   // 37152
    const int SM_LN   = 32 * 513 * 4;    // 65664
    cudaFuncSetAttribute(gemm_pipe, cudaFuncAttributeMaxDynamicSharedMemorySize, SM_GEMM);
    cudaFuncSetAttribute(attn, cudaFuncAttributeMaxDynamicSharedMemorySize, SM_ATTN);
    cudaFuncSetAttribute(ln_fused, cudaFuncAttributeMaxDynamicSharedMemorySize, SM_LN);

    // One-time conversions
    convert_split<<<1024, 256>>>(Wq, Wh + 0 * D_ * D_, Wl + 0 * D_ * D_, D_ * D_);
    convert_split<<<1024, 256>>>(Wk, Wh + 1 * D_ * D_, Wl + 1 * D_ * D_, D_ * D_);
    convert_split<<<1024, 256>>>(Wv, Wh + 2 * D_ * D_, Wl + 2 * D_ * D_, D_ * D_);
    convert_split<<<1024, 256>>>(Wm, Wh + 3 * D_ * D_, Wl + 3 * D_ * D_, D_ * D_);
    transpose_split<<<dim3(NQ_ / 32, D_ / 32), dim3(32, 8)>>>(guide, gh, gl, NQ_);
    transpose_split<<<dim3(NL_ / 32, D_ / 32), dim3(32, 8)>>>(low, lh, ll, NL_);

    // Projections
    gemm_pipe<<<dim3(NQ_ / 128, 4), 256, SM_GEMM>>>(gh, gl, Wh + 0 * D_ * D_, Wl + 0 * D_ * D_, qb);
    gemm_pipe<<<dim3(NL_ / 128, 4), 256, SM_GEMM>>>(lh, ll, Wh + 1 * D_ * D_, Wl + 1 * D_ * D_, Kb);
    gemm_pipe<<<dim3(NL_ / 128, 4), 256, SM_GEMM>>>(lh, ll, Wh + 2 * D_ * D_, Wl + 2 * D_ * D_, Vb);

    // Windowed attention (emits bf16 hi/lo msg)
    attn<<<dim3(32, 32), 128, SM_ATTN>>>(qb, Kb, Vb, mh, ml);

    // Output projection + fused LayerNorm/transpose
    gemm_pipe<<<dim3(NQ_ / 128, 4), 256, SM_GEMM>>>(mh, ml, Wh + 3 * D_ * D_, Wl + 3 * D_ * D_, mT);
    ln_fused<<<NQ_ / 32, 256, SM_LN>>>(mT, gamma, beta, out);
}

// round 5
// speedup vs baseline: 1.1470x; 1.1470x over previous
#include <cuda_runtime.h>
#include <cuda_fp16.h>
#include <cstdint>

#define D_    512
#define NQ_   16384
#define NL_   1024

// ============================ scratch ============================
__device__ __half g_gA[NQ_ * D_];      // guide token-major fp16
__device__ __half g_lA[NL_ * D_];      // low token-major fp16
__device__ __half g_Wh[4][D_ * D_];    // q,k,v,m weight hi fp16
__device__ __half g_Wl[4][D_ * D_];    // weight lo fp16
__device__ float  g_q[NQ_ * D_];
__device__ float  g_K[NL_ * D_];
__device__ float  g_V[NL_ * D_];
__device__ __half g_msg[NQ_ * D_];     // attention output fp16 (exact GEMM2 input)
__device__ float  g_mT[NQ_ * D_];

// ============================ helpers ============================
__device__ __forceinline__ uint32_t smem_u32(const void* p) {
    uint32_t a;
    asm("{ .reg .u64 t; cvta.to.shared.u64 t, %1; cvt.u32.u64 %0, t; }" : "=r"(a) : "l"(p));
    return a;
}
__device__ __forceinline__ void cp16(uint32_t s, const void* g) {
    asm volatile("cp.async.cg.shared.global [%0], [%1], 16;" :: "r"(s), "l"(g));
}
#define CP_COMMIT() asm volatile("cp.async.commit_group;" ::: "memory")
#define CP_WAIT(n)  asm volatile("cp.async.wait_group %0;" :: "n"(n) : "memory")

__device__ __forceinline__ void ldsm_x4(uint32_t* r, uint32_t addr) {
    asm volatile("ldmatrix.sync.aligned.m8n8.x4.shared.b16 {%0,%1,%2,%3}, [%4];"
                 : "=r"(r[0]), "=r"(r[1]), "=r"(r[2]), "=r"(r[3]) : "r"(addr));
}
__device__ __forceinline__ void mma_f16(float* d, const uint32_t* a, uint32_t b0, uint32_t b1) {
    asm volatile(
        "mma.sync.aligned.m16n8k16.row.col.f32.f16.f16.f32 "
        "{%0,%1,%2,%3}, {%4,%5,%6,%7}, {%8,%9}, {%0,%1,%2,%3};"
        : "+f"(d[0]), "+f"(d[1]), "+f"(d[2]), "+f"(d[3])
        : "r"(a[0]), "r"(a[1]), "r"(a[2]), "r"(a[3]), "r"(b0), "r"(b1));
}

// ============================ converts ============================
// 4 weight matrices -> fp16 hi/lo (grid.y selects matrix)
__global__ __launch_bounds__(256)
void wconv(const float* __restrict__ W0, const float* __restrict__ W1,
           const float* __restrict__ W2, const float* __restrict__ W3,
           __half* __restrict__ Wh, __half* __restrict__ Wl) {
    const float* src = (blockIdx.y == 0) ? W0 : (blockIdx.y == 1) ? W1
                     : (blockIdx.y == 2) ? W2 : W3;
    const int i = blockIdx.x * 256 + threadIdx.x;
    const size_t o = (size_t)blockIdx.y * (D_ * D_) + i;
    const float v = src[i];
    const __half h = __float2half(v);
    Wh[o] = h;
    Wl[o] = __float2half(v - __half2float(h));
}

// [512 c][N] fp32 -> [N][512] fp16 token-major
__global__ __launch_bounds__(256)
void transpose_half(const float* __restrict__ x, __half* __restrict__ y, int N) {
    __shared__ float t[32][33];
    const int n0 = blockIdx.x * 32, c0 = blockIdx.y * 32;
    const int tx = threadIdx.x, ty = threadIdx.y;
#pragma unroll
    for (int j = 0; j < 32; j += 8)
        t[ty + j][tx] = x[(size_t)(c0 + ty + j) * N + n0 + tx];
    __syncthreads();
#pragma unroll
    for (int j = 0; j < 32; j += 8)
        y[(size_t)(n0 + ty + j) * D_ + c0 + tx] = __float2half(t[tx][ty + j]);
}

// ============================ GEMM ============================
// C[m,n] = sum_k A[m,k] * (Bh+Bl)[n,k].  A fp16 [M][512], B fp16 [512][512].
// CTA 128m x 128n, k-chunk 64, 2-stage cp.async. 8 warps 2m x 4n. 2 MMAs (hi+lo B).
__global__ __launch_bounds__(256, 2)
void gemm2(const __half* __restrict__ A, const __half* __restrict__ Bh,
           const __half* __restrict__ Bl, float* __restrict__ C) {
    extern __shared__ char sm[];
    const int tid = threadIdx.x, lane = tid & 31, warp = tid >> 5;
    const int wm = (warp & 1) * 64, wn = (warp >> 1) * 32;
    const int m0 = blockIdx.x * 128, n0 = blockIdx.y * 128;
    const uint32_t s0 = smem_u32(sm);
    // stage: A(18432) Bh(18432) Bl(18432); stage stride 55296

    const int l_row = tid >> 1;          // 0..127
    const int l_c0  = tid & 1;           // chunk base

#define LOAD_STAGE(BUF, K0) do {                                                \
    const uint32_t sb = s0 + (BUF) * 55296u;                                    \
    _Pragma("unroll")                                                           \
    for (int it = 0; it < 4; it++) {                                            \
        const int c16 = l_c0 + it * 2;                                          \
        const uint32_t so = (uint32_t)(l_row * 144 + c16 * 16);                 \
        const size_t ga = (size_t)(m0 + l_row) * 512 + (K0) + c16 * 8;          \
        const size_t gb = (size_t)(n0 + l_row) * 512 + (K0) + c16 * 8;          \
        cp16(sb + so,           A  + ga);                                       \
        cp16(sb + 18432u + so,  Bh + gb);                                       \
        cp16(sb + 36864u + so,  Bl + gb);                                       \
    }                                                                           \
} while (0)

    const uint32_t aoff0 = (uint32_t)((wm + (lane & 15)) * 144 + ((lane >> 4) & 1) * 16);
    const uint32_t boff0 = (uint32_t)((wn + (lane & 7) + ((lane >> 4) & 1) * 8) * 144 +
                                      ((lane >> 3) & 1) * 16);

    float acc[4][4][4];
#pragma unroll
    for (int i = 0; i < 4; i++)
#pragma unroll
        for (int j = 0; j < 4; j++)
#pragma unroll
            for (int r = 0; r < 4; r++) acc[i][j][r] = 0.f;

    LOAD_STAGE(0, 0);
    CP_COMMIT();

    for (int ch = 0; ch < 8; ch++) {
        if (ch < 7) { LOAD_STAGE((ch + 1) & 1, (ch + 1) * 64); CP_COMMIT(); }
        if (ch < 7) { CP_WAIT(1); } else { CP_WAIT(0); }
        __syncthreads();

        const uint32_t base = s0 + (uint32_t)(ch & 1) * 55296u;
#pragma unroll
        for (int ks = 0; ks < 4; ks++) {
            uint32_t a[4][4], bh[2][4], bl[2][4];
#pragma unroll
            for (int mi = 0; mi < 4; mi++)
                ldsm_x4(a[mi], base + aoff0 + mi * 16 * 144 + ks * 32);
#pragma unroll
            for (int nt = 0; nt < 2; nt++) {
                const uint32_t bo = boff0 + nt * 16 * 144 + ks * 32;
                ldsm_x4(bh[nt], base + 18432u + bo);
                ldsm_x4(bl[nt], base + 36864u + bo);
            }
#pragma unroll
            for (int mi = 0; mi < 4; mi++) {
#pragma unroll
                for (int j = 0; j < 4; j++) {
                    mma_f16(acc[mi][j], a[mi],
                            bh[j >> 1][(j & 1) * 2], bh[j >> 1][(j & 1) * 2 + 1]);
                    mma_f16(acc[mi][j], a[mi],
                            bl[j >> 1][(j & 1) * 2], bl[j >> 1][(j & 1) * 2 + 1]);
                }
            }
        }
        __syncthreads();
    }

    const int g = lane >> 2, t4 = lane & 3;
#pragma unroll
    for (int mi = 0; mi < 4; mi++) {
#pragma unroll
        for (int j = 0; j < 4; j++) {
            const int row = m0 + wm + mi * 16 + g;
            const int col = n0 + wn + j * 8 + 2 * t4;
            *(float2*)(C + (size_t)row * 512 + col)       = make_float2(acc[mi][j][0], acc[mi][j][1]);
            *(float2*)(C + (size_t)(row + 8) * 512 + col) = make_float2(acc[mi][j][2], acc[mi][j][3]);
        }
    }
#undef LOAD_STAGE
}

// ============================ attention ============================
// q,K,V: fp32 [*,512]; out msg fp16 [NQ,512]. One block per 4x4 guide tile
// (shared 3x3 key window). 128 thr = 16 q x 8 heads. q in registers; smem 37KB.
__global__ __launch_bounds__(128)
void attn(const float* __restrict__ q, const float* __restrict__ Kb,
          const float* __restrict__ Vb, __half* __restrict__ msg) {
    extern __shared__ float4 s4[];
    float4* ks = s4;                 // 9 x 129
    float4* vs = ks + 9 * 129;       // 9 x 129

    const int by = blockIdx.y, bx = blockIdx.x;
    const int tid = threadIdx.x;

    for (int t = tid; t < 1152; t += 128) {
        const int k = t >> 7, i = t & 127;
        const int yy = min(max(by + k / 3 - 1, 0), 31);
        const int xx = min(max(bx + k % 3 - 1, 0), 31);
        const int pos = yy * 32 + xx;
        ks[k * 129 + i] = ((const float4*)(Kb + (size_t)pos * D_))[i];
        vs[k * 129 + i] = ((const float4*)(Vb + (size_t)pos * D_))[i];
    }

    const int qi = tid & 15;
    const int h = tid >> 4;
    const int n = (4 * by + (qi >> 2)) * 128 + 4 * bx + (qi & 3);

    float4 qr[16];
    const float4* qg = (const float4*)(q + (size_t)n * D_ + h * 64);
#pragma unroll
    for (int i = 0; i < 16; i++) qr[i] = qg[i];

    __syncthreads();

    float sc[9];
#pragma unroll
    for (int k = 0; k < 9; k++) {
        const float4* kp = ks + k * 129 + h * 16;
        float s = 0.f;
#pragma unroll
        for (int d4 = 0; d4 < 16; d4++) {
            const float4 a = qr[d4], b = kp[d4];
            s = fmaf(a.x, b.x, s); s = fmaf(a.y, b.y, s);
            s = fmaf(a.z, b.z, s); s = fmaf(a.w, b.w, s);
        }
        sc[k] = s * 0.125f;
    }
    float mx = sc[0];
#pragma unroll
    for (int k = 1; k < 9; k++) mx = fmaxf(mx, sc[k]);
    float sum = 0.f;
#pragma unroll
    for (int k = 0; k < 9; k++) { sc[k] = __expf(sc[k] - mx); sum += sc[k]; }
    const float inv = 1.f / sum;
#pragma unroll
    for (int k = 0; k < 9; k++) sc[k] *= inv;

    __half2* om = (__half2*)(msg + (size_t)n * D_ + h * 64);
#pragma unroll 4
    for (int d4 = 0; d4 < 16; d4++) {
        float ax = 0.f, ay = 0.f, az = 0.f, aw = 0.f;
#pragma unroll
        for (int k = 0; k < 9; k++) {
            const float4 v = vs[k * 129 + h * 16 + d4];
            ax = fmaf(sc[k], v.x, ax); ay = fmaf(sc[k], v.y, ay);
            az = fmaf(sc[k], v.z, az); aw = fmaf(sc[k], v.w, aw);
        }
        om[d4 * 2 + 0] = __floats2half2_rn(ax, ay);
        om[d4 * 2 + 1] = __floats2half2_rn(az, aw);
    }
}

// ============================ fused LayerNorm + transpose ============================
__global__ __launch_bounds__(256)
void ln_fused(const float* __restrict__ m, const float* __restrict__ gamma,
              const float* __restrict__ beta, float* __restrict__ out) {
    extern __shared__ float smf[];            // [32][513]
    __shared__ float smu[32], srs[32];
    const int n0 = blockIdx.x * 32;
    const int tid = threadIdx.x, lane = tid & 31, warp = tid >> 5;

    for (int idx = tid; idx < 32 * 128; idx += 256) {
        const int row = idx >> 7, c4 = idx & 127;
        const float4 v = *(const float4*)(m + (size_t)(n0 + row) * 512 + c4 * 4);
        float* d = smf + row * 513 + c4 * 4;
        d[0] = v.x; d[1] = v.y; d[2] = v.z; d[3] = v.w;
    }
    __syncthreads();

#pragma unroll
    for (int t = warp * 4; t < warp * 4 + 4; t++) {
        float s = 0.f, s2 = 0.f;
#pragma unroll
        for (int i = 0; i < 16; i++) {
            const float v = smf[t * 513 + lane + i * 32];
            s += v; s2 += v * v;
        }
#pragma unroll
        for (int o = 16; o; o >>= 1) {
            s  += __shfl_xor_sync(0xFFFFFFFFu, s, o);
            s2 += __shfl_xor_sync(0xFFFFFFFFu, s2, o);
        }
        if (lane == 0) {
            const float mu = s * (1.f / 512.f);
            smu[t] = mu;
            srs[t] = rsqrtf(s2 * (1.f / 512.f) - mu * mu + 1e-5f);
        }
    }
    __syncthreads();

    for (int idx = tid; idx < 32 * 512; idx += 256) {
        const int c = idx >> 5, nl = idx & 31;
        out[(size_t)c * NQ_ + n0 + nl] =
            (smf[nl * 513 + c] - smu[nl]) * srs[nl] * gamma[c] + beta[c];
    }
}

// ============================ launch ============================
extern "C" void kernel_launch(void* const* d_in, const int* in_sizes, int n_in,
                              void* d_out, int out_size) {
    const float* low   = (const float*)d_in[0];
    const float* guide = (const float*)d_in[1];
    const float* Wq    = (const float*)d_in[2];
    const float* Wk    = (const float*)d_in[3];
    const float* Wv    = (const float*)d_in[4];
    const float* Wm    = (const float*)d_in[5];
    const float* gamma = (const float*)d_in[6];
    const float* beta  = (const float*)d_in[7];
    float* out = (float*)d_out;

    __half *gA, *lA, *Wh, *Wl, *msg;
    float *qb, *Kb, *Vb, *mT;
    cudaGetSymbolAddress((void**)&gA,  g_gA);
    cudaGetSymbolAddress((void**)&lA,  g_lA);
    cudaGetSymbolAddress((void**)&Wh,  g_Wh);
    cudaGetSymbolAddress((void**)&Wl,  g_Wl);
    cudaGetSymbolAddress((void**)&qb,  g_q);
    cudaGetSymbolAddress((void**)&Kb,  g_K);
    cudaGetSymbolAddress((void**)&Vb,  g_V);
    cudaGetSymbolAddress((void**)&msg, g_msg);
    cudaGetSymbolAddress((void**)&mT,  g_mT);

    const int SM_GEMM = 2 * 55296;       // 110592
    const int SM_ATTN = 18 * 129 * 16;   // 37152
    const int SM_LN   = 32 * 513 * 4;    // 65664
    cudaFuncSetAttribute(gemm2, cudaFuncAttributeMaxDynamicSharedMemorySize, SM_GEMM);
    cudaFuncSetAttribute(attn, cudaFuncAttributeMaxDynamicSharedMemorySize, SM_ATTN);
    cudaFuncSetAttribute(ln_fused, cudaFuncAttributeMaxDynamicSharedMemorySize, SM_LN);

    // One-time conversions (weights hi/lo; activations fp16 token-major)
    wconv<<<dim3(D_ * D_ / 256, 4), 256>>>(Wq, Wk, Wv, Wm, Wh, Wl);
    transpose_half<<<dim3(NQ_ / 32, D_ / 32), dim3(32, 8)>>>(guide, gA, NQ_);
    transpose_half<<<dim3(NL_ / 32, D_ / 32), dim3(32, 8)>>>(low, lA, NL_);

    // Projections (2-mma fp16: A * (Wh + Wl))
    gemm2<<<dim3(NQ_ / 128, 4), 256, SM_GEMM>>>(gA, Wh + 0 * D_ * D_, Wl + 0 * D_ * D_, qb);
    gemm2<<<dim3(NL_ / 128, 4), 256, SM_GEMM>>>(lA, Wh + 1 * D_ * D_, Wl + 1 * D_ * D_, Kb);
    gemm2<<<dim3(NL_ / 128, 4), 256, SM_GEMM>>>(lA, Wh + 2 * D_ * D_, Wl + 2 * D_ * D_, Vb);

    // Windowed attention (emits fp16 msg — exact GEMM2 input)
    attn<<<dim3(32, 32), 128, SM_ATTN>>>(qb, Kb, Vb, msg);

    // Output projection + fused LayerNorm/transpose
    gemm2<<<dim3(NQ_ / 128, 4), 256, SM_GEMM>>>(msg, Wh + 3 * D_ * D_, Wl + 3 * D_ * D_, mT);
    ln_fused<<<NQ_ / 32, 256, SM_LN>>>(mT, gamma, beta, out);
}

// round 6
// speedup vs baseline: 1.4373x; 1.2532x over previous
#include <cuda_runtime.h>
#include <cuda_fp16.h>
#include <cstdint>

#define D_    512
#define NQ_   16384
#define NL_   1024

// ============================ scratch ============================
__device__ __half g_gA[NQ_ * D_];      // guide token-major fp16
__device__ __half g_lA[NL_ * D_];      // low token-major fp16
__device__ __half g_Wh[4][D_ * D_];    // q,k,v,m weight hi fp16 (k,v contiguous)
__device__ __half g_Wl[4][D_ * D_];
__device__ float  g_q[NQ_ * D_];
__device__ float  g_KV[NL_ * 1024];    // fused K|V per token
__device__ __half g_msg[NQ_ * D_];
__device__ float  g_mT[NQ_ * D_];

// ============================ helpers ============================
__device__ __forceinline__ uint32_t smem_u32(const void* p) {
    uint32_t a;
    asm("{ .reg .u64 t; cvta.to.shared.u64 t, %1; cvt.u32.u64 %0, t; }" : "=r"(a) : "l"(p));
    return a;
}
__device__ __forceinline__ void cp16(uint32_t s, const void* g) {
    asm volatile("cp.async.cg.shared.global [%0], [%1], 16;" :: "r"(s), "l"(g));
}
#define CP_COMMIT() asm volatile("cp.async.commit_group;" ::: "memory")
#define CP_WAIT(n)  asm volatile("cp.async.wait_group %0;" :: "n"(n) : "memory")

__device__ __forceinline__ void ldsm_x4(uint32_t* r, uint32_t addr) {
    asm volatile("ldmatrix.sync.aligned.m8n8.x4.shared.b16 {%0,%1,%2,%3}, [%4];"
                 : "=r"(r[0]), "=r"(r[1]), "=r"(r[2]), "=r"(r[3]) : "r"(addr));
}
__device__ __forceinline__ void mma_f16(float* d, const uint32_t* a, uint32_t b0, uint32_t b1) {
    asm volatile(
        "mma.sync.aligned.m16n8k16.row.col.f32.f16.f16.f32 "
        "{%0,%1,%2,%3}, {%4,%5,%6,%7}, {%8,%9}, {%0,%1,%2,%3};"
        : "+f"(d[0]), "+f"(d[1]), "+f"(d[2]), "+f"(d[3])
        : "r"(a[0]), "r"(a[1]), "r"(a[2]), "r"(a[3]), "r"(b0), "r"(b1));
}
// 64B-row XOR swizzle: seg' = seg ^ ((row>>1)&3); conflict-free for ldsm + stores
__device__ __forceinline__ uint32_t swz(int row, int seg) {
    return (uint32_t)(row * 64 + ((seg ^ ((row >> 1) & 3)) * 16));
}

// ============================ converts ============================
__global__ __launch_bounds__(256)
void wconv(const float* __restrict__ W0, const float* __restrict__ W1,
           const float* __restrict__ W2, const float* __restrict__ W3,
           __half* __restrict__ Wh, __half* __restrict__ Wl) {
    const float* src = (blockIdx.y == 0) ? W0 : (blockIdx.y == 1) ? W1
                     : (blockIdx.y == 2) ? W2 : W3;
    const int i = blockIdx.x * 256 + threadIdx.x;
    const size_t o = (size_t)blockIdx.y * (D_ * D_) + i;
    const float v = src[i];
    const __half h = __float2half(v);
    Wh[o] = h;
    Wl[o] = __float2half(v - __half2float(h));
}

__global__ __launch_bounds__(256)
void transpose_half(const float* __restrict__ x, __half* __restrict__ y, int N) {
    __shared__ float t[32][33];
    const int n0 = blockIdx.x * 32, c0 = blockIdx.y * 32;
    const int tx = threadIdx.x, ty = threadIdx.y;
#pragma unroll
    for (int j = 0; j < 32; j += 8)
        t[ty + j][tx] = x[(size_t)(c0 + ty + j) * N + n0 + tx];
    __syncthreads();
#pragma unroll
    for (int j = 0; j < 32; j += 8)
        y[(size_t)(n0 + ty + j) * D_ + c0 + tx] = __float2half(t[tx][ty + j]);
}

// ============================ GEMM ============================
// C[m, n0+n] = sum_k A[m,k] * (Bh+Bl)[n0+n,k]; ldc = C row stride.
// CTA 128m x 128n, k-chunk 32, 4-stage cp.async (wait_group 2), 1 sync/chunk.
// 8 warps 2m x 4n. hi-MMA sweep then lo-MMA sweep (breaks acc RAW chains).
__global__ __launch_bounds__(256, 2)
void gemm2(const __half* __restrict__ A, const __half* __restrict__ Bh,
           const __half* __restrict__ Bl, float* __restrict__ C, int ldc) {
    extern __shared__ char sm[];
    const int tid = threadIdx.x, lane = tid & 31, warp = tid >> 5;
    const int wm = (warp & 1) * 64, wn = (warp >> 1) * 32;
    const int m0 = blockIdx.x * 128, n0 = blockIdx.y * 128;
    const uint32_t s0 = smem_u32(sm);
    // stage: A(8192) Bh(8192) Bl(8192) = 24576; 4 stages = 98304

    const int l_row = tid >> 1;           // 0..127
    const int l_s0  = (tid & 1) * 2;      // seg pair

#define LOAD_STAGE(BUF, K0) do {                                                \
    const uint32_t sb = s0 + (uint32_t)(BUF) * 24576u;                          \
    _Pragma("unroll")                                                           \
    for (int j = 0; j < 2; j++) {                                               \
        const int seg = l_s0 + j;                                               \
        const uint32_t so = swz(l_row, seg);                                    \
        const size_t ga = (size_t)(m0 + l_row) * 512 + (K0) + seg * 8;          \
        const size_t gb = (size_t)(n0 + l_row) * 512 + (K0) + seg * 8;          \
        cp16(sb + so,           A  + ga);                                       \
        cp16(sb + 8192u  + so,  Bh + gb);                                       \
        cp16(sb + 16384u + so,  Bl + gb);                                       \
    }                                                                           \
} while (0)

    // ldsm lane addressing (swizzled)
    int a_rb[4], a_rx[4];
#pragma unroll
    for (int mi = 0; mi < 4; mi++) {
        const int r = wm + mi * 16 + (lane & 15);
        a_rb[mi] = r * 64;
        a_rx[mi] = (r >> 1) & 3;
    }
    int b_rb[2], b_rx[2];
#pragma unroll
    for (int nt = 0; nt < 2; nt++) {
        const int r = wn + nt * 16 + (lane & 7) + ((lane >> 4) & 1) * 8;
        b_rb[nt] = r * 64;
        b_rx[nt] = (r >> 1) & 3;
    }
    const int a_sl = (lane >> 4) & 1;
    const int b_sl = (lane >> 3) & 1;

    float acc[4][4][4];
#pragma unroll
    for (int i = 0; i < 4; i++)
#pragma unroll
        for (int j = 0; j < 4; j++)
#pragma unroll
            for (int r = 0; r < 4; r++) acc[i][j][r] = 0.f;

    LOAD_STAGE(0, 0);  CP_COMMIT();
    LOAD_STAGE(1, 32); CP_COMMIT();
    LOAD_STAGE(2, 64); CP_COMMIT();

    for (int ch = 0; ch < 16; ch++) {
        CP_WAIT(2);
        __syncthreads();

        const uint32_t base = s0 + (uint32_t)(ch & 3) * 24576u;
#pragma unroll
        for (int ks = 0; ks < 2; ks++) {
            uint32_t a[4][4], bh[2][4], bl[2][4];
            const int sa = ks * 2 + a_sl;
            const int sb = ks * 2 + b_sl;
#pragma unroll
            for (int mi = 0; mi < 4; mi++)
                ldsm_x4(a[mi], base + a_rb[mi] + ((sa ^ a_rx[mi]) * 16));
#pragma unroll
            for (int nt = 0; nt < 2; nt++) {
                const uint32_t bo = b_rb[nt] + ((sb ^ b_rx[nt]) * 16);
                ldsm_x4(bh[nt], base + 8192u  + bo);
                ldsm_x4(bl[nt], base + 16384u + bo);
            }
#pragma unroll
            for (int mi = 0; mi < 4; mi++)
#pragma unroll
                for (int j = 0; j < 4; j++)
                    mma_f16(acc[mi][j], a[mi],
                            bh[j >> 1][(j & 1) * 2], bh[j >> 1][(j & 1) * 2 + 1]);
#pragma unroll
            for (int mi = 0; mi < 4; mi++)
#pragma unroll
                for (int j = 0; j < 4; j++)
                    mma_f16(acc[mi][j], a[mi],
                            bl[j >> 1][(j & 1) * 2], bl[j >> 1][(j & 1) * 2 + 1]);
        }
        if (ch < 13) LOAD_STAGE((ch + 3) & 3, (ch + 3) * 32);
        CP_COMMIT();
    }

    const int g = lane >> 2, t4 = lane & 3;
#pragma unroll
    for (int mi = 0; mi < 4; mi++) {
#pragma unroll
        for (int j = 0; j < 4; j++) {
            const int row = m0 + wm + mi * 16 + g;
            const int col = n0 + wn + j * 8 + 2 * t4;
            *(float2*)(C + (size_t)row * ldc + col)       = make_float2(acc[mi][j][0], acc[mi][j][1]);
            *(float2*)(C + (size_t)(row + 8) * ldc + col) = make_float2(acc[mi][j][2], acc[mi][j][3]);
        }
    }
#undef LOAD_STAGE
}

// ============================ attention ============================
// q fp32 [NQ,512]; KV fp32 [NL,1024] (K|V); msg fp16 [NQ,512].
__global__ __launch_bounds__(128)
void attn(const float* __restrict__ q, const float* __restrict__ KV,
          __half* __restrict__ msg) {
    extern __shared__ float4 s4[];
    float4* ks = s4;                 // 9 x 129
    float4* vs = ks + 9 * 129;       // 9 x 129

    const int by = blockIdx.y, bx = blockIdx.x;
    const int tid = threadIdx.x;

    for (int t = tid; t < 1152; t += 128) {
        const int k = t >> 7, i = t & 127;
        const int yy = min(max(by + k / 3 - 1, 0), 31);
        const int xx = min(max(bx + k % 3 - 1, 0), 31);
        const float4* row = (const float4*)(KV + (size_t)(yy * 32 + xx) * 1024);
        ks[k * 129 + i] = row[i];
        vs[k * 129 + i] = row[128 + i];
    }

    const int qi = tid & 15;
    const int h = tid >> 4;
    const int n = (4 * by + (qi >> 2)) * 128 + 4 * bx + (qi & 3);

    float4 qr[16];
    const float4* qg = (const float4*)(q + (size_t)n * D_ + h * 64);
#pragma unroll
    for (int i = 0; i < 16; i++) qr[i] = qg[i];

    __syncthreads();

    float sc[9];
#pragma unroll
    for (int k = 0; k < 9; k++) {
        const float4* kp = ks + k * 129 + h * 16;
        float s = 0.f;
#pragma unroll
        for (int d4 = 0; d4 < 16; d4++) {
            const float4 a = qr[d4], b = kp[d4];
            s = fmaf(a.x, b.x, s); s = fmaf(a.y, b.y, s);
            s = fmaf(a.z, b.z, s); s = fmaf(a.w, b.w, s);
        }
        sc[k] = s * 0.125f;
    }
    float mx = sc[0];
#pragma unroll
    for (int k = 1; k < 9; k++) mx = fmaxf(mx, sc[k]);
    float sum = 0.f;
#pragma unroll
    for (int k = 0; k < 9; k++) { sc[k] = __expf(sc[k] - mx); sum += sc[k]; }
    const float inv = 1.f / sum;
#pragma unroll
    for (int k = 0; k < 9; k++) sc[k] *= inv;

    __half2* om = (__half2*)(msg + (size_t)n * D_ + h * 64);
#pragma unroll 4
    for (int d4 = 0; d4 < 16; d4++) {
        float ax = 0.f, ay = 0.f, az = 0.f, aw = 0.f;
#pragma unroll
        for (int k = 0; k < 9; k++) {
            const float4 v = vs[k * 129 + h * 16 + d4];
            ax = fmaf(sc[k], v.x, ax); ay = fmaf(sc[k], v.y, ay);
            az = fmaf(sc[k], v.z, az); aw = fmaf(sc[k], v.w, aw);
        }
        om[d4 * 2 + 0] = __floats2half2_rn(ax, ay);
        om[d4 * 2 + 1] = __floats2half2_rn(az, aw);
    }
}

// ============================ fused LayerNorm + transpose ============================
__global__ __launch_bounds__(256)
void ln_fused(const float* __restrict__ m, const float* __restrict__ gamma,
              const float* __restrict__ beta, float* __restrict__ out) {
    extern __shared__ float smf[];            // [32][513]
    __shared__ float smu[32], srs[32];
    const int n0 = blockIdx.x * 32;
    const int tid = threadIdx.x, lane = tid & 31, warp = tid >> 5;

    for (int idx = tid; idx < 32 * 128; idx += 256) {
        const int row = idx >> 7, c4 = idx & 127;
        const float4 v = *(const float4*)(m + (size_t)(n0 + row) * 512 + c4 * 4);
        float* d = smf + row * 513 + c4 * 4;
        d[0] = v.x; d[1] = v.y; d[2] = v.z; d[3] = v.w;
    }
    __syncthreads();

#pragma unroll
    for (int t = warp * 4; t < warp * 4 + 4; t++) {
        float s = 0.f, s2 = 0.f;
#pragma unroll
        for (int i = 0; i < 16; i++) {
            const float v = smf[t * 513 + lane + i * 32];
            s += v; s2 += v * v;
        }
#pragma unroll
        for (int o = 16; o; o >>= 1) {
            s  += __shfl_xor_sync(0xFFFFFFFFu, s, o);
            s2 += __shfl_xor_sync(0xFFFFFFFFu, s2, o);
        }
        if (lane == 0) {
            const float mu = s * (1.f / 512.f);
            smu[t] = mu;
            srs[t] = rsqrtf(s2 * (1.f / 512.f) - mu * mu + 1e-5f);
        }
    }
    __syncthreads();

    for (int idx = tid; idx < 32 * 512; idx += 256) {
        const int c = idx >> 5, nl = idx & 31;
        out[(size_t)c * NQ_ + n0 + nl] =
            (smf[nl * 513 + c] - smu[nl]) * srs[nl] * gamma[c] + beta[c];
    }
}

// ============================ launch ============================
extern "C" void kernel_launch(void* const* d_in, const int* in_sizes, int n_in,
                              void* d_out, int out_size) {
    const float* low   = (const float*)d_in[0];
    const float* guide = (const float*)d_in[1];
    const float* Wq    = (const float*)d_in[2];
    const float* Wk    = (const float*)d_in[3];
    const float* Wv    = (const float*)d_in[4];
    const float* Wm    = (const float*)d_in[5];
    const float* gamma = (const float*)d_in[6];
    const float* beta  = (const float*)d_in[7];
    float* out = (float*)d_out;

    __half *gA, *lA, *Wh, *Wl, *msg;
    float *qb, *KV, *mT;
    cudaGetSymbolAddress((void**)&gA,  g_gA);
    cudaGetSymbolAddress((void**)&lA,  g_lA);
    cudaGetSymbolAddress((void**)&Wh,  g_Wh);
    cudaGetSymbolAddress((void**)&Wl,  g_Wl);
    cudaGetSymbolAddress((void**)&qb,  g_q);
    cudaGetSymbolAddress((void**)&KV,  g_KV);
    cudaGetSymbolAddress((void**)&msg, g_msg);
    cudaGetSymbolAddress((void**)&mT,  g_mT);

    const int SM_GEMM = 4 * 24576;       // 98304
    const int SM_ATTN = 18 * 129 * 16;   // 37152
    const int SM_LN   = 32 * 513 * 4;    // 65664
    cudaFuncSetAttribute(gemm2, cudaFuncAttributeMaxDynamicSharedMemorySize, SM_GEMM);
    cudaFuncSetAttribute(attn, cudaFuncAttributeMaxDynamicSharedMemorySize, SM_ATTN);
    cudaFuncSetAttribute(ln_fused, cudaFuncAttributeMaxDynamicSharedMemorySize, SM_LN);

    // One-time conversions
    wconv<<<dim3(D_ * D_ / 256, 4), 256>>>(Wq, Wk, Wv, Wm, Wh, Wl);
    transpose_half<<<dim3(NQ_ / 32, D_ / 32), dim3(32, 8)>>>(guide, gA, NQ_);
    transpose_half<<<dim3(NL_ / 32, D_ / 32), dim3(32, 8)>>>(low, lA, NL_);

    // Q projection
    gemm2<<<dim3(NQ_ / 128, 4), 256, SM_GEMM>>>(gA, Wh + 0 * (D_ * D_), Wl + 0 * (D_ * D_), qb, 512);
    // Fused K|V projection (Wk,Wv contiguous -> B [1024,512], C [1024,1024])
    gemm2<<<dim3(NL_ / 128, 8), 256, SM_GEMM>>>(lA, Wh + 1 * (D_ * D_), Wl + 1 * (D_ * D_), KV, 1024);

    // Windowed attention (emits fp16 msg)
    attn<<<dim3(32, 32), 128, SM_ATTN>>>(qb, KV, msg);

    // Output projection + fused LayerNorm/transpose
    gemm2<<<dim3(NQ_ / 128, 4), 256, SM_GEMM>>>(msg, Wh + 3 * (D_ * D_), Wl + 3 * (D_ * D_), mT, 512);
    ln_fused<<<NQ_ / 32, 256, SM_LN>>>(mT, gamma, beta, out);
}

// round 7
// speedup vs baseline: 1.5173x; 1.0556x over previous
#include <cuda_runtime.h>
#include <cuda_fp16.h>
#include <cstdint>

#define D_    512
#define NQ_   16384
#define NL_   1024

// ============================ scratch ============================
__device__ __half g_gA[NQ_ * D_];      // guide token-major fp16
__device__ __half g_lA[NL_ * D_];      // low token-major fp16
__device__ __half g_Wh[4][D_ * D_];    // q,k,v,m weight hi fp16 (k,v contiguous)
__device__ __half g_Wl[4][D_ * D_];
__device__ float  g_q[NQ_ * D_];
__device__ float  g_KV[NL_ * 1024];    // fused K|V per token
__device__ __half g_msg[NQ_ * D_];
__device__ float  g_mT[NQ_ * D_];

// ============================ helpers ============================
__device__ __forceinline__ uint32_t smem_u32(const void* p) {
    uint32_t a;
    asm("{ .reg .u64 t; cvta.to.shared.u64 t, %1; cvt.u32.u64 %0, t; }" : "=r"(a) : "l"(p));
    return a;
}
__device__ __forceinline__ void cp16(uint32_t s, const void* g) {
    asm volatile("cp.async.cg.shared.global [%0], [%1], 16;" :: "r"(s), "l"(g));
}
#define CP_COMMIT() asm volatile("cp.async.commit_group;" ::: "memory")
#define CP_WAIT(n)  asm volatile("cp.async.wait_group %0;" :: "n"(n) : "memory")

__device__ __forceinline__ void ldsm_x4(uint32_t* r, uint32_t addr) {
    asm volatile("ldmatrix.sync.aligned.m8n8.x4.shared.b16 {%0,%1,%2,%3}, [%4];"
                 : "=r"(r[0]), "=r"(r[1]), "=r"(r[2]), "=r"(r[3]) : "r"(addr));
}
__device__ __forceinline__ void mma_f16(float* d, const uint32_t* a, uint32_t b0, uint32_t b1) {
    asm volatile(
        "mma.sync.aligned.m16n8k16.row.col.f32.f16.f16.f32 "
        "{%0,%1,%2,%3}, {%4,%5,%6,%7}, {%8,%9}, {%0,%1,%2,%3};"
        : "+f"(d[0]), "+f"(d[1]), "+f"(d[2]), "+f"(d[3])
        : "r"(a[0]), "r"(a[1]), "r"(a[2]), "r"(a[3]), "r"(b0), "r"(b1));
}
__device__ __forceinline__ uint32_t swz(int row, int seg) {
    return (uint32_t)(row * 64 + ((seg ^ ((row >> 1) & 3)) * 16));
}

// ============================ converts ============================
__global__ __launch_bounds__(256)
void wconv(const float* __restrict__ W0, const float* __restrict__ W1,
           const float* __restrict__ W2, const float* __restrict__ W3,
           __half* __restrict__ Wh, __half* __restrict__ Wl) {
    const float* src = (blockIdx.y == 0) ? W0 : (blockIdx.y == 1) ? W1
                     : (blockIdx.y == 2) ? W2 : W3;
    const int i = blockIdx.x * 256 + threadIdx.x;
    const size_t o = (size_t)blockIdx.y * (D_ * D_) + i;
    const float v = src[i];
    const __half h = __float2half(v);
    Wh[o] = h;
    Wl[o] = __float2half(v - __half2float(h));
}

__global__ __launch_bounds__(256)
void transpose_half(const float* __restrict__ x, __half* __restrict__ y, int N) {
    __shared__ float t[32][33];
    const int n0 = blockIdx.x * 32, c0 = blockIdx.y * 32;
    const int tx = threadIdx.x, ty = threadIdx.y;
#pragma unroll
    for (int j = 0; j < 32; j += 8)
        t[ty + j][tx] = x[(size_t)(c0 + ty + j) * N + n0 + tx];
    __syncthreads();
#pragma unroll
    for (int j = 0; j < 32; j += 8)
        y[(size_t)(n0 + ty + j) * D_ + c0 + tx] = __float2half(t[tx][ty + j]);
}

// ============================ GEMM body ============================
// C[m0+m, n0+n] = sum_k A[m,k] * (Bh+Bl)[n,k]. 4-stage cp.async, k-chunk 32,
// prefetch issued immediately after barrier (overlaps full compute block).
__device__ __forceinline__
void gemm_body(const __half* __restrict__ A, const __half* __restrict__ Bh,
               const __half* __restrict__ Bl, float* __restrict__ C,
               int ldc, int m0, int n0) {
    extern __shared__ char sm[];
    const int tid = threadIdx.x, lane = tid & 31, warp = tid >> 5;
    const int wm = (warp & 1) * 64, wn = (warp >> 1) * 32;
    const uint32_t s0 = smem_u32(sm);

    const int l_row = tid >> 1;
    const int l_s0  = (tid & 1) * 2;

#define LOAD_STAGE(BUF, K0) do {                                                \
    const uint32_t sb = s0 + (uint32_t)(BUF) * 24576u;                          \
    _Pragma("unroll")                                                           \
    for (int j = 0; j < 2; j++) {                                               \
        const int seg = l_s0 + j;                                               \
        const uint32_t so = swz(l_row, seg);                                    \
        const size_t ga = (size_t)(m0 + l_row) * 512 + (K0) + seg * 8;          \
        const size_t gb = (size_t)(n0 + l_row) * 512 + (K0) + seg * 8;          \
        cp16(sb + so,           A  + ga);                                       \
        cp16(sb + 8192u  + so,  Bh + gb);                                       \
        cp16(sb + 16384u + so,  Bl + gb);                                       \
    }                                                                           \
} while (0)

    int a_rb[4], a_rx[4];
#pragma unroll
    for (int mi = 0; mi < 4; mi++) {
        const int r = wm + mi * 16 + (lane & 15);
        a_rb[mi] = r * 64;
        a_rx[mi] = (r >> 1) & 3;
    }
    int b_rb[2], b_rx[2];
#pragma unroll
    for (int nt = 0; nt < 2; nt++) {
        const int r = wn + nt * 16 + (lane & 7) + ((lane >> 4) & 1) * 8;
        b_rb[nt] = r * 64;
        b_rx[nt] = (r >> 1) & 3;
    }
    const int a_sl = (lane >> 4) & 1;
    const int b_sl = (lane >> 3) & 1;

    float acc[4][4][4];
#pragma unroll
    for (int i = 0; i < 4; i++)
#pragma unroll
        for (int j = 0; j < 4; j++)
#pragma unroll
            for (int r = 0; r < 4; r++) acc[i][j][r] = 0.f;

    LOAD_STAGE(0, 0);  CP_COMMIT();
    LOAD_STAGE(1, 32); CP_COMMIT();
    LOAD_STAGE(2, 64); CP_COMMIT();

    for (int ch = 0; ch < 16; ch++) {
        CP_WAIT(2);
        __syncthreads();
        // prefetch FIRST: overlaps the whole compute block below
        if (ch < 13) LOAD_STAGE((ch + 3) & 3, (ch + 3) * 32);
        CP_COMMIT();

        const uint32_t base = s0 + (uint32_t)(ch & 3) * 24576u;
#pragma unroll
        for (int ks = 0; ks < 2; ks++) {
            uint32_t a[4][4], bh[2][4], bl[2][4];
            const int sa = ks * 2 + a_sl;
            const int sb = ks * 2 + b_sl;
#pragma unroll
            for (int mi = 0; mi < 4; mi++)
                ldsm_x4(a[mi], base + a_rb[mi] + ((sa ^ a_rx[mi]) * 16));
#pragma unroll
            for (int nt = 0; nt < 2; nt++) {
                const uint32_t bo = b_rb[nt] + ((sb ^ b_rx[nt]) * 16);
                ldsm_x4(bh[nt], base + 8192u  + bo);
                ldsm_x4(bl[nt], base + 16384u + bo);
            }
#pragma unroll
            for (int mi = 0; mi < 4; mi++)
#pragma unroll
                for (int j = 0; j < 4; j++)
                    mma_f16(acc[mi][j], a[mi],
                            bh[j >> 1][(j & 1) * 2], bh[j >> 1][(j & 1) * 2 + 1]);
#pragma unroll
            for (int mi = 0; mi < 4; mi++)
#pragma unroll
                for (int j = 0; j < 4; j++)
                    mma_f16(acc[mi][j], a[mi],
                            bl[j >> 1][(j & 1) * 2], bl[j >> 1][(j & 1) * 2 + 1]);
        }
    }

    const int g = lane >> 2, t4 = lane & 3;
#pragma unroll
    for (int mi = 0; mi < 4; mi++) {
#pragma unroll
        for (int j = 0; j < 4; j++) {
            const int row = m0 + wm + mi * 16 + g;
            const int col = n0 + wn + j * 8 + 2 * t4;
            *(float2*)(C + (size_t)row * ldc + col)       = make_float2(acc[mi][j][0], acc[mi][j][1]);
            *(float2*)(C + (size_t)(row + 8) * ldc + col) = make_float2(acc[mi][j][2], acc[mi][j][3]);
        }
    }
#undef LOAD_STAGE
}

// Fused Q-proj (512 CTAs) + KV-proj (64 CTAs) in one launch.
__global__ __launch_bounds__(256, 2)
void gemm_qkv(const __half* __restrict__ gA, const __half* __restrict__ lA,
              const __half* __restrict__ Wh, const __half* __restrict__ Wl,
              float* __restrict__ qb, float* __restrict__ KV) {
    const int bid = blockIdx.x;
    if (bid < 64) {
        // KV: A = lA [1024 x 512]; B = Wk|Wv [1024 x 512]; C = KV [1024 x 1024]
        const int m0 = (bid >> 3) * 128;
        const int n0 = (bid & 7) * 128;
        gemm_body(lA, Wh + (size_t)(D_ * D_), Wl + (size_t)(D_ * D_), KV, 1024, m0, n0);
    } else {
        const int b = bid - 64;
        const int m0 = (b >> 2) * 128;
        const int n0 = (b & 3) * 128;
        gemm_body(gA, Wh, Wl, qb, 512, m0, n0);
    }
}

// Single GEMM (output projection)
__global__ __launch_bounds__(256, 2)
void gemm_one(const __half* __restrict__ A, const __half* __restrict__ Bh,
              const __half* __restrict__ Bl, float* __restrict__ C) {
    gemm_body(A, Bh, Bl, C, 512, blockIdx.x * 128, blockIdx.y * 128);
}

// ============================ attention ============================
// Two horizontally-adjacent 4x4 tiles per block: shared 3x4 K/V window (12 rows).
// 256 thr = 2 tiles x 16 q x 8 heads. smem 49.5KB -> 4 CTAs/SM.
__global__ __launch_bounds__(256)
void attn(const float* __restrict__ q, const float* __restrict__ KV,
          __half* __restrict__ msg) {
    extern __shared__ float4 s4[];
    float4* ks = s4;                  // 12 x 129
    float4* vs = ks + 12 * 129;       // 12 x 129

    const int by = blockIdx.y;        // 0..31
    const int xb = blockIdx.x * 2;    // tile0 x (0..30 even)
    const int tid = threadIdx.x;

    for (int t = tid; t < 3072; t += 256) {
        const int r = t >> 7, i = t & 127;        // r 0..23
        const int k = (r < 12) ? r : r - 12;
        const int ky = k >> 2, kx = k & 3;
        const int yy = min(max(by + ky - 1, 0), 31);
        const int xx = min(max(xb + kx - 1, 0), 31);
        const float4* row = (const float4*)(KV + (size_t)(yy * 32 + xx) * 1024);
        if (r < 12) ks[k * 129 + i] = row[i];
        else        vs[k * 129 + i] = row[128 + i];
    }

    const int qi = tid & 15;
    const int h  = (tid >> 4) & 7;
    const int ti = tid >> 7;                       // which tile
    const int n = (4 * by + (qi >> 2)) * 128 + 4 * (xb + ti) + (qi & 3);

    float4 qr[16];
    const float4* qg = (const float4*)(q + (size_t)n * D_ + h * 64);
#pragma unroll
    for (int i = 0; i < 16; i++) qr[i] = qg[i];

    __syncthreads();

    float sc[9];
#pragma unroll
    for (int ky = 0; ky < 3; ky++)
#pragma unroll
    for (int kx = 0; kx < 3; kx++) {
        const float4* kp = ks + (ky * 4 + kx + ti) * 129 + h * 16;
        float s = 0.f;
#pragma unroll
        for (int d4 = 0; d4 < 16; d4++) {
            const float4 a = qr[d4], b = kp[d4];
            s = fmaf(a.x, b.x, s); s = fmaf(a.y, b.y, s);
            s = fmaf(a.z, b.z, s); s = fmaf(a.w, b.w, s);
        }
        sc[ky * 3 + kx] = s * 0.125f;
    }
    float mx = sc[0];
#pragma unroll
    for (int k = 1; k < 9; k++) mx = fmaxf(mx, sc[k]);
    float sum = 0.f;
#pragma unroll
    for (int k = 0; k < 9; k++) { sc[k] = __expf(sc[k] - mx); sum += sc[k]; }
    const float inv = 1.f / sum;
#pragma unroll
    for (int k = 0; k < 9; k++) sc[k] *= inv;

    __half2* om = (__half2*)(msg + (size_t)n * D_ + h * 64);
#pragma unroll 4
    for (int d4 = 0; d4 < 16; d4++) {
        float ax = 0.f, ay = 0.f, az = 0.f, aw = 0.f;
#pragma unroll
        for (int ky = 0; ky < 3; ky++)
#pragma unroll
        for (int kx = 0; kx < 3; kx++) {
            const float4 v = vs[(ky * 4 + kx + ti) * 129 + h * 16 + d4];
            const float w = sc[ky * 3 + kx];
            ax = fmaf(w, v.x, ax); ay = fmaf(w, v.y, ay);
            az = fmaf(w, v.z, az); aw = fmaf(w, v.w, aw);
        }
        om[d4 * 2 + 0] = __floats2half2_rn(ax, ay);
        om[d4 * 2 + 1] = __floats2half2_rn(az, aw);
    }
}

// ============================ fused LayerNorm + transpose ============================
__global__ __launch_bounds__(256)
void ln_fused(const float* __restrict__ m, const float* __restrict__ gamma,
              const float* __restrict__ beta, float* __restrict__ out) {
    extern __shared__ float smf[];            // [32][513]
    __shared__ float smu[32], srs[32];
    const int n0 = blockIdx.x * 32;
    const int tid = threadIdx.x, lane = tid & 31, warp = tid >> 5;

    for (int idx = tid; idx < 32 * 128; idx += 256) {
        const int row = idx >> 7, c4 = idx & 127;
        const float4 v = *(const float4*)(m + (size_t)(n0 + row) * 512 + c4 * 4);
        float* d = smf + row * 513 + c4 * 4;
        d[0] = v.x; d[1] = v.y; d[2] = v.z; d[3] = v.w;
    }
    __syncthreads();

#pragma unroll
    for (int t = warp * 4; t < warp * 4 + 4; t++) {
        float s = 0.f, s2 = 0.f;
#pragma unroll
        for (int i = 0; i < 16; i++) {
            const float v = smf[t * 513 + lane + i * 32];
            s += v; s2 += v * v;
        }
#pragma unroll
        for (int o = 16; o; o >>= 1) {
            s  += __shfl_xor_sync(0xFFFFFFFFu, s, o);
            s2 += __shfl_xor_sync(0xFFFFFFFFu, s2, o);
        }
        if (lane == 0) {
            const float mu = s * (1.f / 512.f);
            smu[t] = mu;
            srs[t] = rsqrtf(s2 * (1.f / 512.f) - mu * mu + 1e-5f);
        }
    }
    __syncthreads();

    for (int idx = tid; idx < 32 * 512; idx += 256) {
        const int c = idx >> 5, nl = idx & 31;
        out[(size_t)c * NQ_ + n0 + nl] =
            (smf[nl * 513 + c] - smu[nl]) * srs[nl] * gamma[c] + beta[c];
    }
}

// ============================ launch ============================
extern "C" void kernel_launch(void* const* d_in, const int* in_sizes, int n_in,
                              void* d_out, int out_size) {
    const float* low   = (const float*)d_in[0];
    const float* guide = (const float*)d_in[1];
    const float* Wq    = (const float*)d_in[2];
    const float* Wk    = (const float*)d_in[3];
    const float* Wv    = (const float*)d_in[4];
    const float* Wm    = (const float*)d_in[5];
    const float* gamma = (const float*)d_in[6];
    const float* beta  = (const float*)d_in[7];
    float* out = (float*)d_out;

    __half *gA, *lA, *Wh, *Wl, *msg;
    float *qb, *KV, *mT;
    cudaGetSymbolAddress((void**)&gA,  g_gA);
    cudaGetSymbolAddress((void**)&lA,  g_lA);
    cudaGetSymbolAddress((void**)&Wh,  g_Wh);
    cudaGetSymbolAddress((void**)&Wl,  g_Wl);
    cudaGetSymbolAddress((void**)&qb,  g_q);
    cudaGetSymbolAddress((void**)&KV,  g_KV);
    cudaGetSymbolAddress((void**)&msg, g_msg);
    cudaGetSymbolAddress((void**)&mT,  g_mT);

    const int SM_GEMM = 4 * 24576;       // 98304
    const int SM_ATTN = 24 * 129 * 16;   // 49536
    const int SM_LN   = 32 * 513 * 4;    // 65664
    cudaFuncSetAttribute(gemm_qkv, cudaFuncAttributeMaxDynamicSharedMemorySize, SM_GEMM);
    cudaFuncSetAttribute(gemm_one, cudaFuncAttributeMaxDynamicSharedMemorySize, SM_GEMM);
    cudaFuncSetAttribute(attn, cudaFuncAttributeMaxDynamicSharedMemorySize, SM_ATTN);
    cudaFuncSetAttribute(ln_fused, cudaFuncAttributeMaxDynamicSharedMemorySize, SM_LN);

    // One-time conversions
    wconv<<<dim3(D_ * D_ / 256, 4), 256>>>(Wq, Wk, Wv, Wm, Wh, Wl);
    transpose_half<<<dim3(NQ_ / 32, D_ / 32), dim3(32, 8)>>>(guide, gA, NQ_);
    transpose_half<<<dim3(NL_ / 32, D_ / 32), dim3(32, 8)>>>(low, lA, NL_);

    // Fused Q + KV projections (576 CTAs, one launch)
    gemm_qkv<<<576, 256, SM_GEMM>>>(gA, lA, Wh, Wl, qb, KV);

    // Windowed attention (2 tiles/block, shared window)
    attn<<<dim3(16, 32), 256, SM_ATTN>>>(qb, KV, msg);

    // Output projection + fused LayerNorm/transpose
    gemm_one<<<dim3(NQ_ / 128, 4), 256, SM_GEMM>>>(msg, Wh + 3 * (D_ * D_), Wl + 3 * (D_ * D_), mT);
    ln_fused<<<NQ_ / 32, 256, SM_LN>>>(mT, gamma, beta, out);
}

// round 8
// speedup vs baseline: 1.7775x; 1.1715x over previous
#include <cuda_runtime.h>
#include <cuda_fp16.h>
#include <cstdint>

#define D_    512
#define NQ_   16384
#define NL_   1024

// ============================ scratch ============================
__device__ __half g_gA[NQ_ * D_];      // guide token-major fp16
__device__ __half g_lA[NL_ * D_];      // low token-major fp16
__device__ __half g_W[4][D_ * D_];     // q,k,v,m weights fp16 (k,v contiguous)
__device__ __half g_q[NQ_ * D_];       // q fp16
__device__ float  g_KV[NL_ * 1024];    // fused K|V per token
__device__ __half g_msg[NQ_ * D_];
__device__ float  g_mT[NQ_ * D_];

// ============================ helpers ============================
__device__ __forceinline__ uint32_t smem_u32(const void* p) {
    uint32_t a;
    asm("{ .reg .u64 t; cvta.to.shared.u64 t, %1; cvt.u32.u64 %0, t; }" : "=r"(a) : "l"(p));
    return a;
}
__device__ __forceinline__ void cp16(uint32_t s, const void* g) {
    asm volatile("cp.async.cg.shared.global [%0], [%1], 16;" :: "r"(s), "l"(g));
}
#define CP_COMMIT() asm volatile("cp.async.commit_group;" ::: "memory")
#define CP_WAIT(n)  asm volatile("cp.async.wait_group %0;" :: "n"(n) : "memory")

__device__ __forceinline__ void ldsm_x4(uint32_t* r, uint32_t addr) {
    asm volatile("ldmatrix.sync.aligned.m8n8.x4.shared.b16 {%0,%1,%2,%3}, [%4];"
                 : "=r"(r[0]), "=r"(r[1]), "=r"(r[2]), "=r"(r[3]) : "r"(addr));
}
__device__ __forceinline__ void mma_f16(float* d, const uint32_t* a, uint32_t b0, uint32_t b1) {
    asm volatile(
        "mma.sync.aligned.m16n8k16.row.col.f32.f16.f16.f32 "
        "{%0,%1,%2,%3}, {%4,%5,%6,%7}, {%8,%9}, {%0,%1,%2,%3};"
        : "+f"(d[0]), "+f"(d[1]), "+f"(d[2]), "+f"(d[3])
        : "r"(a[0]), "r"(a[1]), "r"(a[2]), "r"(a[3]), "r"(b0), "r"(b1));
}
__device__ __forceinline__ uint32_t swz(int row, int seg) {
    return (uint32_t)(row * 64 + ((seg ^ ((row >> 1) & 3)) * 16));
}

// ============================ converts ============================
__global__ __launch_bounds__(256)
void wconv(const float* __restrict__ W0, const float* __restrict__ W1,
           const float* __restrict__ W2, const float* __restrict__ W3,
           __half* __restrict__ W) {
    const float* src = (blockIdx.y == 0) ? W0 : (blockIdx.y == 1) ? W1
                     : (blockIdx.y == 2) ? W2 : W3;
    const int i = blockIdx.x * 256 + threadIdx.x;
    W[(size_t)blockIdx.y * (D_ * D_) + i] = __float2half(src[i]);
}

__global__ __launch_bounds__(256)
void transpose_half(const float* __restrict__ x, __half* __restrict__ y, int N) {
    __shared__ float t[32][33];
    const int n0 = blockIdx.x * 32, c0 = blockIdx.y * 32;
    const int tx = threadIdx.x, ty = threadIdx.y;
#pragma unroll
    for (int j = 0; j < 32; j += 8)
        t[ty + j][tx] = x[(size_t)(c0 + ty + j) * N + n0 + tx];
    __syncthreads();
#pragma unroll
    for (int j = 0; j < 32; j += 8)
        y[(size_t)(n0 + ty + j) * D_ + c0 + tx] = __float2half(t[tx][ty + j]);
}

// ============================ GEMM body ============================
// C[m0+m, n0+n] = sum_k A[m,k]*B[n,k], fp16 in, fp32 acc. 5-stage cp.async,
// k-chunk 32, 1 sync/chunk, prefetch right after barrier.
// OUT_HALF: 0 -> float C, 1 -> __half C.
template<int OUT_HALF>
__device__ __forceinline__
void gemm_body(const __half* __restrict__ A, const __half* __restrict__ B,
               void* __restrict__ C, int ldc, int m0, int n0) {
    extern __shared__ char sm[];
    const int tid = threadIdx.x, lane = tid & 31, warp = tid >> 5;
    const int wm = (warp & 1) * 64, wn = (warp >> 1) * 32;
    const uint32_t s0 = smem_u32(sm);
    // stage: A(8192) B(8192) = 16384; 5 stages = 81920

    const int l_row = tid >> 1;
    const int l_s0  = (tid & 1) * 2;

#define LOAD_STAGE(BUF, K0) do {                                                \
    const uint32_t sb = s0 + (uint32_t)(BUF) * 16384u;                          \
    _Pragma("unroll")                                                           \
    for (int j = 0; j < 2; j++) {                                               \
        const int seg = l_s0 + j;                                               \
        const uint32_t so = swz(l_row, seg);                                    \
        cp16(sb + so,          A + (size_t)(m0 + l_row) * 512 + (K0) + seg * 8);\
        cp16(sb + 8192u + so,  B + (size_t)(n0 + l_row) * 512 + (K0) + seg * 8);\
    }                                                                           \
} while (0)

    int a_rb[4], a_rx[4];
#pragma unroll
    for (int mi = 0; mi < 4; mi++) {
        const int r = wm + mi * 16 + (lane & 15);
        a_rb[mi] = r * 64;
        a_rx[mi] = (r >> 1) & 3;
    }
    int b_rb[2], b_rx[2];
#pragma unroll
    for (int nt = 0; nt < 2; nt++) {
        const int r = wn + nt * 16 + (lane & 7) + ((lane >> 4) & 1) * 8;
        b_rb[nt] = r * 64;
        b_rx[nt] = (r >> 1) & 3;
    }
    const int a_sl = (lane >> 4) & 1;
    const int b_sl = (lane >> 3) & 1;

    float acc[4][4][4];
#pragma unroll
    for (int i = 0; i < 4; i++)
#pragma unroll
        for (int j = 0; j < 4; j++)
#pragma unroll
            for (int r = 0; r < 4; r++) acc[i][j][r] = 0.f;

    LOAD_STAGE(0, 0);  CP_COMMIT();
    LOAD_STAGE(1, 32); CP_COMMIT();
    LOAD_STAGE(2, 64); CP_COMMIT();
    LOAD_STAGE(3, 96); CP_COMMIT();

    int buf = 0, pbuf = 4;
    for (int ch = 0; ch < 16; ch++) {
        CP_WAIT(3);
        __syncthreads();
        if (ch < 12) LOAD_STAGE(pbuf, (ch + 4) * 32);
        CP_COMMIT();

        const uint32_t base = s0 + (uint32_t)buf * 16384u;
#pragma unroll
        for (int ks = 0; ks < 2; ks++) {
            uint32_t a[4][4], b[2][4];
            const int sa = ks * 2 + a_sl;
            const int sb = ks * 2 + b_sl;
#pragma unroll
            for (int mi = 0; mi < 4; mi++)
                ldsm_x4(a[mi], base + a_rb[mi] + ((sa ^ a_rx[mi]) * 16));
#pragma unroll
            for (int nt = 0; nt < 2; nt++)
                ldsm_x4(b[nt], base + 8192u + b_rb[nt] + ((sb ^ b_rx[nt]) * 16));
#pragma unroll
            for (int mi = 0; mi < 4; mi++)
#pragma unroll
                for (int j = 0; j < 4; j++)
                    mma_f16(acc[mi][j], a[mi],
                            b[j >> 1][(j & 1) * 2], b[j >> 1][(j & 1) * 2 + 1]);
        }
        buf  = (buf == 4)  ? 0 : buf + 1;
        pbuf = (pbuf == 4) ? 0 : pbuf + 1;
    }

    const int g = lane >> 2, t4 = lane & 3;
#pragma unroll
    for (int mi = 0; mi < 4; mi++) {
#pragma unroll
        for (int j = 0; j < 4; j++) {
            const int row = m0 + wm + mi * 16 + g;
            const int col = n0 + wn + j * 8 + 2 * t4;
            if (OUT_HALF) {
                __half* Ch = (__half*)C;
                *(__half2*)(Ch + (size_t)row * ldc + col) =
                    __floats2half2_rn(acc[mi][j][0], acc[mi][j][1]);
                *(__half2*)(Ch + (size_t)(row + 8) * ldc + col) =
                    __floats2half2_rn(acc[mi][j][2], acc[mi][j][3]);
            } else {
                float* Cf = (float*)C;
                *(float2*)(Cf + (size_t)row * ldc + col)       = make_float2(acc[mi][j][0], acc[mi][j][1]);
                *(float2*)(Cf + (size_t)(row + 8) * ldc + col) = make_float2(acc[mi][j][2], acc[mi][j][3]);
            }
        }
    }
#undef LOAD_STAGE
}

// Fused Q-proj (512 CTAs, half out) + KV-proj (64 CTAs, float out).
__global__ __launch_bounds__(256, 2)
void gemm_qkv(const __half* __restrict__ gA, const __half* __restrict__ lA,
              const __half* __restrict__ W,
              __half* __restrict__ qb, float* __restrict__ KV) {
    const int bid = blockIdx.x;
    if (bid < 64) {
        const int m0 = (bid >> 3) * 128;
        const int n0 = (bid & 7) * 128;
        gemm_body<0>(lA, W + (size_t)(D_ * D_), KV, 1024, m0, n0);
    } else {
        const int b = bid - 64;
        const int m0 = (b >> 2) * 128;
        const int n0 = (b & 3) * 128;
        gemm_body<1>(gA, W, qb, 512, m0, n0);
    }
}

__global__ __launch_bounds__(256, 2)
void gemm_one(const __half* __restrict__ A, const __half* __restrict__ B,
              float* __restrict__ C) {
    gemm_body<0>(A, B, C, 512, blockIdx.x * 128, blockIdx.y * 128);
}

// ============================ attention ============================
// q fp16 [NQ,512]; KV fp32 [NL,1024]; msg fp16. 2 adjacent 4x4 tiles per block.
__global__ __launch_bounds__(256)
void attn(const __half* __restrict__ q, const float* __restrict__ KV,
          __half* __restrict__ msg) {
    extern __shared__ float4 s4[];
    float4* ks = s4;                  // 12 x 129
    float4* vs = ks + 12 * 129;       // 12 x 129

    const int by = blockIdx.y;
    const int xb = blockIdx.x * 2;
    const int tid = threadIdx.x;

    for (int t = tid; t < 3072; t += 256) {
        const int r = t >> 7, i = t & 127;
        const int k = (r < 12) ? r : r - 12;
        const int ky = k >> 2, kx = k & 3;
        const int yy = min(max(by + ky - 1, 0), 31);
        const int xx = min(max(xb + kx - 1, 0), 31);
        const float4* row = (const float4*)(KV + (size_t)(yy * 32 + xx) * 1024);
        if (r < 12) ks[k * 129 + i] = row[i];
        else        vs[k * 129 + i] = row[128 + i];
    }

    const int qi = tid & 15;
    const int h  = (tid >> 4) & 7;
    const int ti = tid >> 7;
    const int n = (4 * by + (qi >> 2)) * 128 + 4 * (xb + ti) + (qi & 3);

    // q: 64 halfs -> 16 float4 in registers
    float4 qr[16];
    {
        const __half2* qg = (const __half2*)(q + (size_t)n * D_ + h * 64);
#pragma unroll
        for (int i = 0; i < 16; i++) {
            const float2 a = __half22float2(qg[2 * i]);
            const float2 b = __half22float2(qg[2 * i + 1]);
            qr[i] = make_float4(a.x, a.y, b.x, b.y);
        }
    }
    __syncthreads();

    float sc[9];
#pragma unroll
    for (int ky = 0; ky < 3; ky++)
#pragma unroll
    for (int kx = 0; kx < 3; kx++) {
        const float4* kp = ks + (ky * 4 + kx + ti) * 129 + h * 16;
        float s = 0.f;
#pragma unroll
        for (int d4 = 0; d4 < 16; d4++) {
            const float4 a = qr[d4], b = kp[d4];
            s = fmaf(a.x, b.x, s); s = fmaf(a.y, b.y, s);
            s = fmaf(a.z, b.z, s); s = fmaf(a.w, b.w, s);
        }
        sc[ky * 3 + kx] = s * 0.125f;
    }
    float mx = sc[0];
#pragma unroll
    for (int k = 1; k < 9; k++) mx = fmaxf(mx, sc[k]);
    float sum = 0.f;
#pragma unroll
    for (int k = 0; k < 9; k++) { sc[k] = __expf(sc[k] - mx); sum += sc[k]; }
    const float inv = 1.f / sum;
#pragma unroll
    for (int k = 0; k < 9; k++) sc[k] *= inv;

    __half2* om = (__half2*)(msg + (size_t)n * D_ + h * 64);
#pragma unroll 4
    for (int d4 = 0; d4 < 16; d4++) {
        float ax = 0.f, ay = 0.f, az = 0.f, aw = 0.f;
#pragma unroll
        for (int ky = 0; ky < 3; ky++)
#pragma unroll
        for (int kx = 0; kx < 3; kx++) {
            const float4 v = vs[(ky * 4 + kx + ti) * 129 + h * 16 + d4];
            const float w = sc[ky * 3 + kx];
            ax = fmaf(w, v.x, ax); ay = fmaf(w, v.y, ay);
            az = fmaf(w, v.z, az); aw = fmaf(w, v.w, aw);
        }
        om[d4 * 2 + 0] = __floats2half2_rn(ax, ay);
        om[d4 * 2 + 1] = __floats2half2_rn(az, aw);
    }
}

// ============================ fused LayerNorm + transpose ============================
__global__ __launch_bounds__(256)
void ln_fused(const float* __restrict__ m, const float* __restrict__ gamma,
              const float* __restrict__ beta, float* __restrict__ out) {
    extern __shared__ float smf[];            // [32][513]
    __shared__ float smu[32], srs[32];
    const int n0 = blockIdx.x * 32;
    const int tid = threadIdx.x, lane = tid & 31, warp = tid >> 5;

    for (int idx = tid; idx < 32 * 128; idx += 256) {
        const int row = idx >> 7, c4 = idx & 127;
        const float4 v = *(const float4*)(m + (size_t)(n0 + row) * 512 + c4 * 4);
        float* d = smf + row * 513 + c4 * 4;
        d[0] = v.x; d[1] = v.y; d[2] = v.z; d[3] = v.w;
    }
    __syncthreads();

#pragma unroll
    for (int t = warp * 4; t < warp * 4 + 4; t++) {
        float s = 0.f, s2 = 0.f;
#pragma unroll
        for (int i = 0; i < 16; i++) {
            const float v = smf[t * 513 + lane + i * 32];
            s += v; s2 += v * v;
        }
#pragma unroll
        for (int o = 16; o; o >>= 1) {
            s  += __shfl_xor_sync(0xFFFFFFFFu, s, o);
            s2 += __shfl_xor_sync(0xFFFFFFFFu, s2, o);
        }
        if (lane == 0) {
            const float mu = s * (1.f / 512.f);
            smu[t] = mu;
            srs[t] = rsqrtf(s2 * (1.f / 512.f) - mu * mu + 1e-5f);
        }
    }
    __syncthreads();

    for (int idx = tid; idx < 32 * 512; idx += 256) {
        const int c = idx >> 5, nl = idx & 31;
        out[(size_t)c * NQ_ + n0 + nl] =
            (smf[nl * 513 + c] - smu[nl]) * srs[nl] * gamma[c] + beta[c];
    }
}

// ============================ launch ============================
extern "C" void kernel_launch(void* const* d_in, const int* in_sizes, int n_in,
                              void* d_out, int out_size) {
    const float* low   = (const float*)d_in[0];
    const float* guide = (const float*)d_in[1];
    const float* Wq    = (const float*)d_in[2];
    const float* Wk    = (const float*)d_in[3];
    const float* Wv    = (const float*)d_in[4];
    const float* Wm    = (const float*)d_in[5];
    const float* gamma = (const float*)d_in[6];
    const float* beta  = (const float*)d_in[7];
    float* out = (float*)d_out;

    __half *gA, *lA, *W, *qb, *msg;
    float *KV, *mT;
    cudaGetSymbolAddress((void**)&gA,  g_gA);
    cudaGetSymbolAddress((void**)&lA,  g_lA);
    cudaGetSymbolAddress((void**)&W,   g_W);
    cudaGetSymbolAddress((void**)&qb,  g_q);
    cudaGetSymbolAddress((void**)&KV,  g_KV);
    cudaGetSymbolAddress((void**)&msg, g_msg);
    cudaGetSymbolAddress((void**)&mT,  g_mT);

    const int SM_GEMM = 5 * 16384;       // 81920
    const int SM_ATTN = 24 * 129 * 16;   // 49536
    const int SM_LN   = 32 * 513 * 4;    // 65664
    cudaFuncSetAttribute(gemm_qkv, cudaFuncAttributeMaxDynamicSharedMemorySize, SM_GEMM);
    cudaFuncSetAttribute(gemm_one, cudaFuncAttributeMaxDynamicSharedMemorySize, SM_GEMM);
    cudaFuncSetAttribute(attn, cudaFuncAttributeMaxDynamicSharedMemorySize, SM_ATTN);
    cudaFuncSetAttribute(ln_fused, cudaFuncAttributeMaxDynamicSharedMemorySize, SM_LN);

    // One-time conversions
    wconv<<<dim3(D_ * D_ / 256, 4), 256>>>(Wq, Wk, Wv, Wm, W);
    transpose_half<<<dim3(NQ_ / 32, D_ / 32), dim3(32, 8)>>>(guide, gA, NQ_);
    transpose_half<<<dim3(NL_ / 32, D_ / 32), dim3(32, 8)>>>(low, lA, NL_);

    // Fused Q + KV projections
    gemm_qkv<<<576, 256, SM_GEMM>>>(gA, lA, W, qb, KV);

    // Windowed attention
    attn<<<dim3(16, 32), 256, SM_ATTN>>>(qb, KV, msg);

    // Output projection + fused LayerNorm/transpose
    gemm_one<<<dim3(NQ_ / 128, 4), 256, SM_GEMM>>>(msg, W + 3 * (size_t)(D_ * D_), mT);
    ln_fused<<<NQ_ / 32, 256, SM_LN>>>(mT, gamma, beta, out);
}